// round 4
// baseline (speedup 1.0000x reference)
#include <cuda_runtime.h>
#include <cuda_bf16.h>
#include <cstdint>
#include <math.h>

// Problem dims (fixed by the dataset)
constexpr int S  = 8192;   // B*T tokens
constexpr int D  = 2048;   // model dim
constexpr int H  = 2048;   // expert hidden
constexpr int E  = 8;      // experts
constexpr int KK = 2;      // top-k
constexpr int CAP = 2048;  // per-expert capacity
constexpr int B  = 4;
constexpr int T  = 2048;
constexpr int NTILES = H / 128;  // 16 N-tiles per expert row

// ---------------- device scratch (no allocations allowed) ----------------
__device__ int   g_eid[KK * S];
__device__ float g_wgt[KK * S];
__device__ int   g_src[E * CAP];       // slot -> source token (-1 = empty)
__device__ int   g_tokslot[KK * S];    // (k,s) -> slot index or -1
__device__ float g_w2sum[E * H];
__device__ float g_b2sum[E];
__device__ float g_part[(size_t)E * CAP * NTILES];
__device__ float g_logit[S];

// ---------------- K0: row sums of w2 (and b2) --------------------------
__global__ void k_rowsum(const float* __restrict__ src, float* __restrict__ dst,
                         int nrows) {
    int gw   = (blockIdx.x * blockDim.x + threadIdx.x) >> 5;
    int lane = threadIdx.x & 31;
    if (gw >= nrows) return;
    const float* row = src + (size_t)gw * D;
    float s = 0.f;
    #pragma unroll
    for (int d = lane * 4; d < D; d += 32 * 4) {
        float4 v = *(const float4*)(row + d);
        s += v.x + v.y + v.z + v.w;
    }
    #pragma unroll
    for (int o = 16; o; o >>= 1) s += __shfl_xor_sync(0xffffffffu, s, o);
    if (lane == 0) dst[gw] = s;
}

// ---------------- K1: gating (top-2 of softmax(x@wg), normalized) ------
__global__ void k_gate(const float* __restrict__ x, const float* __restrict__ wg) {
    int warp = (blockIdx.x * blockDim.x + threadIdx.x) >> 5;
    int lane = threadIdx.x & 31;
    if (warp >= S) return;
    const float* xr = x + (size_t)warp * D;
    float acc[8] = {0, 0, 0, 0, 0, 0, 0, 0};
    for (int d = lane; d < D; d += 32) {
        float xv = xr[d];
        const float* wr = wg + (size_t)d * 8;
        float4 w0 = *(const float4*)wr;
        float4 w1 = *(const float4*)(wr + 4);
        acc[0] = fmaf(xv, w0.x, acc[0]);
        acc[1] = fmaf(xv, w0.y, acc[1]);
        acc[2] = fmaf(xv, w0.z, acc[2]);
        acc[3] = fmaf(xv, w0.w, acc[3]);
        acc[4] = fmaf(xv, w1.x, acc[4]);
        acc[5] = fmaf(xv, w1.y, acc[5]);
        acc[6] = fmaf(xv, w1.z, acc[6]);
        acc[7] = fmaf(xv, w1.w, acc[7]);
    }
    #pragma unroll
    for (int ee = 0; ee < 8; ee++)
        #pragma unroll
        for (int o = 16; o; o >>= 1)
            acc[ee] += __shfl_xor_sync(0xffffffffu, acc[ee], o);
    if (lane == 0) {
        // top-1 (strict > keeps lowest index on ties, matching lax.top_k)
        int i0 = 0; float v0 = acc[0];
        #pragma unroll
        for (int ee = 1; ee < 8; ee++)
            if (acc[ee] > v0) { v0 = acc[ee]; i0 = ee; }
        int i1 = -1; float v1 = -INFINITY;
        #pragma unroll
        for (int ee = 0; ee < 8; ee++)
            if (ee != i0 && acc[ee] > v1) { v1 = acc[ee]; i1 = ee; }
        // normalized top-2 softmax weights: w0 = e^{v0}/(e^{v0}+e^{v1})
        float w0 = 1.f / (1.f + __expf(0.f) * expf(v1 - v0));
        g_eid[warp]     = i0;
        g_eid[S + warp] = i1;
        g_wgt[warp]     = w0;
        g_wgt[S + warp] = 1.f - w0;
    }
}

// ---------------- K2: capacity-aware slot assignment (one block) -------
// Exact k-major, s-minor rank per expert (matches cumsum semantics).
__global__ void k_assign() {
    __shared__ int hist[256][8];
    const int t = threadIdx.x;
    // init slot map
    for (int i = t; i < E * CAP; i += 256) g_src[i] = -1;
    // local histogram over this thread's 64 consecutive (k-major) entries
    int h[8] = {0, 0, 0, 0, 0, 0, 0, 0};
    const int base = t * 64;
    for (int j = 0; j < 64; j++) h[g_eid[base + j]]++;
    #pragma unroll
    for (int ee = 0; ee < 8; ee++) hist[t][ee] = h[ee];
    __syncthreads();
    // exclusive scan over chunks, per expert (serial, tiny)
    if (t < 8) {
        int run = 0;
        for (int c = 0; c < 256; c++) {
            int v = hist[c][t];
            hist[c][t] = run;
            run += v;
        }
    }
    __syncthreads();
    int cnt[8];
    #pragma unroll
    for (int ee = 0; ee < 8; ee++) cnt[ee] = hist[t][ee];
    for (int j = 0; j < 64; j++) {
        int n = base + j;
        int e = g_eid[n];
        int loc = cnt[e]++;
        if (loc < CAP) {
            g_src[e * CAP + loc] = n & (S - 1);  // token s
            g_tokslot[n] = e * CAP + loc;
        } else {
            g_tokslot[n] = -1;
        }
    }
}

// ---------------- K3: fused expert GEMM + epilogue reduction -----------
// grid = (H/128, CAP/128, E). Block computes 128x128 tile of
// h = relu(gather(x) @ w1[e] + b1[e]) and reduces h . w2sum[e] per row,
// writing one partial per (slot, n-tile) into g_part. No atomics.
__global__ void __launch_bounds__(256, 2)
k_ffn(const float* __restrict__ x, const float* __restrict__ w1,
      const float* __restrict__ b1) {
    const int e  = blockIdx.z;
    const int m0 = blockIdx.y * 128;
    const int n0 = blockIdx.x * 128;
    const int t  = threadIdx.x;

    __shared__ float As[2][8][132];  // padded (+4) to dodge STS conflicts
    __shared__ float Bs[2][8][128];

    // A loader: 128 rows x 8 k per tile; 2 threads per row
    const int arow  = t >> 1;
    const int ahalf = (t & 1) * 4;
    const int stok  = g_src[e * CAP + m0 + arow];
    const float* aptr = (stok >= 0) ? (x + (size_t)stok * D + ahalf) : nullptr;

    // B loader: 8 k x 128 n per tile
    const int bk = t >> 5;
    const int bn = (t & 31) * 4;
    const float* bptr = w1 + ((size_t)e * D + bk) * H + n0 + bn;

    float4 areg = make_float4(0.f, 0.f, 0.f, 0.f);
    if (aptr) areg = *(const float4*)aptr;
    float4 breg = *(const float4*)bptr;

    As[0][ahalf + 0][arow] = areg.x;
    As[0][ahalf + 1][arow] = areg.y;
    As[0][ahalf + 2][arow] = areg.z;
    As[0][ahalf + 3][arow] = areg.w;
    *(float4*)&Bs[0][bk][bn] = breg;
    __syncthreads();

    const int ty = t >> 4, tx = t & 15;
    float acc[8][8];
    #pragma unroll
    for (int i = 0; i < 8; i++)
        #pragma unroll
        for (int j = 0; j < 8; j++) acc[i][j] = 0.f;

    int buf = 0;
    for (int kk = 8; kk <= D; kk += 8) {
        const bool more = (kk < D);
        if (more) {
            areg = make_float4(0.f, 0.f, 0.f, 0.f);
            if (aptr) areg = *(const float4*)(aptr + kk);
            breg = *(const float4*)(bptr + (size_t)kk * H);
        }
        #pragma unroll
        for (int k = 0; k < 8; k++) {
            float a[8], b[8];
            *(float4*)&a[0] = *(const float4*)&As[buf][k][ty * 8];
            *(float4*)&a[4] = *(const float4*)&As[buf][k][ty * 8 + 4];
            *(float4*)&b[0] = *(const float4*)&Bs[buf][k][tx * 8];
            *(float4*)&b[4] = *(const float4*)&Bs[buf][k][tx * 8 + 4];
            #pragma unroll
            for (int i = 0; i < 8; i++)
                #pragma unroll
                for (int j = 0; j < 8; j++)
                    acc[i][j] = fmaf(a[i], b[j], acc[i][j]);
        }
        if (more) {
            const int nb = buf ^ 1;
            As[nb][ahalf + 0][arow] = areg.x;
            As[nb][ahalf + 1][arow] = areg.y;
            As[nb][ahalf + 2][arow] = areg.z;
            As[nb][ahalf + 3][arow] = areg.w;
            *(float4*)&Bs[nb][bk][bn] = breg;
        }
        __syncthreads();
        buf ^= 1;
    }

    // Epilogue: relu(acc + b1) . w2sum, reduced across the 16 tx columns.
    float bv[8], wv[8];
    {
        const float* bp = b1 + (size_t)e * H + n0 + tx * 8;
        const float* wp = g_w2sum + (size_t)e * H + n0 + tx * 8;
        *(float4*)&bv[0] = *(const float4*)bp;
        *(float4*)&bv[4] = *(const float4*)(bp + 4);
        *(float4*)&wv[0] = *(const float4*)wp;
        *(float4*)&wv[4] = *(const float4*)(wp + 4);
    }
    float* red = &As[0][0][0];  // 2112 floats available, need 2048
    #pragma unroll
    for (int i = 0; i < 8; i++) {
        float sr = 0.f;
        #pragma unroll
        for (int j = 0; j < 8; j++)
            sr += fmaxf(acc[i][j] + bv[j], 0.f) * wv[j];
        red[tx * 128 + ty * 8 + i] = sr;
    }
    __syncthreads();
    if (t < 128) {
        float ssum = 0.f;
        #pragma unroll
        for (int q = 0; q < 16; q++) ssum += red[q * 128 + t];
        g_part[(size_t)(e * CAP + m0 + t) * NTILES + blockIdx.x] = ssum;
    }
}

// ---------------- K4a: per-token logit = sum over D of y ----------------
__global__ void k_logit() {
    int s = blockIdx.x * blockDim.x + threadIdx.x;
    if (s >= S) return;
    float l = 0.f;
    #pragma unroll
    for (int k = 0; k < KK; k++) {
        int slot = g_tokslot[k * S + s];
        if (slot >= 0) {
            float c = 0.f;
            const float* p = g_part + (size_t)slot * NTILES;
            #pragma unroll
            for (int j = 0; j < NTILES; j++) c += p[j];
            l += g_wgt[k * S + s] * (c + g_b2sum[g_eid[k * S + s]]);
        }
    }
    g_logit[s] = l;
}

// ---------------- K4b: log_softmax over T per batch row -----------------
__global__ void k_lsm(float* __restrict__ out) {
    const int b = blockIdx.x;
    const int t = threadIdx.x;  // 256 threads
    __shared__ float sh[256];
    const float* lr = g_logit + (size_t)b * T;
    float v[8];
    float mx = -INFINITY;
    #pragma unroll
    for (int i = 0; i < 8; i++) {
        v[i] = lr[t + i * 256];
        mx = fmaxf(mx, v[i]);
    }
    sh[t] = mx;
    __syncthreads();
    for (int o = 128; o; o >>= 1) {
        if (t < o) sh[t] = fmaxf(sh[t], sh[t + o]);
        __syncthreads();
    }
    mx = sh[0];
    __syncthreads();
    float se = 0.f;
    #pragma unroll
    for (int i = 0; i < 8; i++) se += expf(v[i] - mx);
    sh[t] = se;
    __syncthreads();
    for (int o = 128; o; o >>= 1) {
        if (t < o) sh[t] += sh[t + o];
        __syncthreads();
    }
    float lse = logf(sh[0]) + mx;
    #pragma unroll
    for (int i = 0; i < 8; i++)
        out[(size_t)b * T + t + i * 256] = v[i] - lse;
}

// ---------------- launch ------------------------------------------------
extern "C" void kernel_launch(void* const* d_in, const int* in_sizes, int n_in,
                              void* d_out, int out_size) {
    const float* x  = (const float*)d_in[0];   // [B,T,D]
    const float* wg = (const float*)d_in[1];   // [D,E]
    const float* w1 = (const float*)d_in[2];   // [E,D,H]
    const float* b1 = (const float*)d_in[3];   // [E,H]
    const float* w2 = (const float*)d_in[4];   // [E,H,D]
    const float* b2 = (const float*)d_in[5];   // [E,D]
    float* out = (float*)d_out;                // [B,T]
    (void)in_sizes; (void)n_in; (void)out_size;

    float* w2sum_p; cudaGetSymbolAddress((void**)&w2sum_p, g_w2sum);
    float* b2sum_p; cudaGetSymbolAddress((void**)&b2sum_p, g_b2sum);

    // K0: w2 row sums (E*H rows of length D) and b2 sums (E rows)
    k_rowsum<<<(E * H) / 8, 256>>>(w2, w2sum_p, E * H);
    k_rowsum<<<1, 256>>>(b2, b2sum_p, E);

    // K1: gating, one warp per token
    k_gate<<<S / 8, 256>>>(x, wg);

    // K2: deterministic capacity assignment, single block
    k_assign<<<1, 256>>>();

    // K3: grouped expert GEMM + fused reduction
    dim3 g3(H / 128, CAP / 128, E);
    k_ffn<<<g3, 256>>>(x, w1, b1);

    // K4: combine + log_softmax
    k_logit<<<S / 256, 256>>>();
    k_lsm<<<B, 256>>>(out);
}

// round 6
// speedup vs baseline: 2.6487x; 2.6487x over previous
#include <cuda_runtime.h>
#include <cuda_bf16.h>
#include <cstdint>
#include <math.h>

// Problem dims (fixed by the dataset)
constexpr int S  = 8192;   // B*T tokens
constexpr int D  = 2048;   // model dim
constexpr int H  = 2048;   // expert hidden
constexpr int E  = 8;      // experts
constexpr int KK = 2;      // top-k
constexpr int CAP = 2048;  // per-expert capacity
constexpr int B  = 4;
constexpr int T  = 2048;

// GEMM tiling (HMMA path: CTA 128x128, 8 warps = 2M x 4N, warp 64x32)
constexpr int MT = 128;
constexpr int NTT = 128;
constexpr int KTILE = 32;            // k elements per stage
constexpr int STAGES = 4;
constexpr int NK = D / KTILE;        // 64 stages
constexpr int NTILES = H / NTT;      // 16 N-tiles per expert row
constexpr int ASTAGE = MT * 128;     // 16384 B (row = 32 hi bf16 | 32 lo bf16 = 128 B)
constexpr int BSTAGE = NTT * 128;    // 16384 B
constexpr int SMEM_FFN = STAGES * (ASTAGE + BSTAGE);  // 131072 B

// ---------------- device scratch (no allocations allowed) ----------------
__device__ int   g_eid[KK * S];
__device__ float g_wgt[KK * S];
__device__ int   g_src[E * CAP];       // slot -> source token (-1 = empty)
__device__ int   g_tokslot[KK * S];    // (k,s) -> slot index or -1
__device__ float g_w2sum[E * H];
__device__ float g_b2sum[E];
__device__ float g_part[(size_t)E * CAP * NTILES];
__device__ float g_logit[S];
// bf16 hi/lo split operands
__device__ __nv_bfloat16 g_ah[(size_t)E * CAP * D];    // gathered tokens, hi
__device__ __nv_bfloat16 g_al[(size_t)E * CAP * D];    // gathered tokens, lo
__device__ __nv_bfloat16 g_w1h[(size_t)E * H * D];     // w1^T [E][H][D], hi
__device__ __nv_bfloat16 g_w1l[(size_t)E * H * D];     // w1^T, lo

// ---------------- PTX helpers (baseline ISA only: sm_80-class) ----------
__device__ __forceinline__ uint32_t s2u(const void* p) {
    return (uint32_t)__cvta_generic_to_shared(p);
}
__device__ __forceinline__ void cpa16(uint32_t s, const void* g) {
    asm volatile("cp.async.cg.shared.global [%0], [%1], 16;" :: "r"(s), "l"(g));
}
__device__ __forceinline__ void cp_commit() {
    asm volatile("cp.async.commit_group;" ::: "memory");
}
template <int N>
__device__ __forceinline__ void cp_wait() {
    asm volatile("cp.async.wait_group %0;" :: "n"(N) : "memory");
}
__device__ __forceinline__ void ldsm4(uint32_t* r, uint32_t addr) {
    asm volatile("ldmatrix.sync.aligned.m8n8.x4.shared.b16 {%0,%1,%2,%3}, [%4];"
                 : "=r"(r[0]), "=r"(r[1]), "=r"(r[2]), "=r"(r[3]) : "r"(addr));
}
__device__ __forceinline__ void mma16816(float* c, const uint32_t* a,
                                         uint32_t b0, uint32_t b1) {
    asm volatile(
        "mma.sync.aligned.m16n8k16.row.col.f32.bf16.bf16.f32 "
        "{%0,%1,%2,%3}, {%4,%5,%6,%7}, {%8,%9}, {%0,%1,%2,%3};"
        : "+f"(c[0]), "+f"(c[1]), "+f"(c[2]), "+f"(c[3])
        : "r"(a[0]), "r"(a[1]), "r"(a[2]), "r"(a[3]), "r"(b0), "r"(b1));
}
__device__ __forceinline__ uint32_t swz(uint32_t off) {
    return off ^ ((off >> 3) & 0x70);
}

// ---------------- K0: row sums of w2 (and b2) --------------------------
__global__ void k_rowsum(const float* __restrict__ src, float* __restrict__ dst,
                         int nrows) {
    int gw   = (blockIdx.x * blockDim.x + threadIdx.x) >> 5;
    int lane = threadIdx.x & 31;
    if (gw >= nrows) return;
    const float* row = src + (size_t)gw * D;
    float s = 0.f;
    #pragma unroll
    for (int d = lane * 4; d < D; d += 32 * 4) {
        float4 v = *(const float4*)(row + d);
        s += v.x + v.y + v.z + v.w;
    }
    #pragma unroll
    for (int o = 16; o; o >>= 1) s += __shfl_xor_sync(0xffffffffu, s, o);
    if (lane == 0) dst[gw] = s;
}

// ---------------- K0b: w1 transpose + bf16 hi/lo split ------------------
__global__ void k_convw1(const float* __restrict__ w1) {
    __shared__ float ts[32][33];
    const int e  = blockIdx.z;
    const int h0 = blockIdx.x * 32;
    const int d0 = blockIdx.y * 32;
    const int tx = threadIdx.x & 31, ty = threadIdx.x >> 5;  // 256 thr
    #pragma unroll
    for (int j = 0; j < 4; j++)
        ts[ty + 8 * j][tx] = w1[((size_t)e * D + d0 + ty + 8 * j) * H + h0 + tx];
    __syncthreads();
    #pragma unroll
    for (int j = 0; j < 4; j++) {
        float v = ts[tx][ty + 8 * j];
        size_t o = ((size_t)e * H + h0 + ty + 8 * j) * D + d0 + tx;
        __nv_bfloat16 hi = __float2bfloat16(v);
        g_w1h[o] = hi;
        g_w1l[o] = __float2bfloat16(v - __bfloat162float(hi));
    }
}

// ---------------- K1: gating (top-2 of softmax(x@wg), normalized) ------
__global__ void k_gate(const float* __restrict__ x, const float* __restrict__ wg) {
    int warp = (blockIdx.x * blockDim.x + threadIdx.x) >> 5;
    int lane = threadIdx.x & 31;
    if (warp >= S) return;
    const float* xr = x + (size_t)warp * D;
    float acc[8] = {0, 0, 0, 0, 0, 0, 0, 0};
    for (int d = lane; d < D; d += 32) {
        float xv = xr[d];
        const float* wr = wg + (size_t)d * 8;
        float4 w0 = *(const float4*)wr;
        float4 w1 = *(const float4*)(wr + 4);
        acc[0] = fmaf(xv, w0.x, acc[0]);
        acc[1] = fmaf(xv, w0.y, acc[1]);
        acc[2] = fmaf(xv, w0.z, acc[2]);
        acc[3] = fmaf(xv, w0.w, acc[3]);
        acc[4] = fmaf(xv, w1.x, acc[4]);
        acc[5] = fmaf(xv, w1.y, acc[5]);
        acc[6] = fmaf(xv, w1.z, acc[6]);
        acc[7] = fmaf(xv, w1.w, acc[7]);
    }
    #pragma unroll
    for (int ee = 0; ee < 8; ee++)
        #pragma unroll
        for (int o = 16; o; o >>= 1)
            acc[ee] += __shfl_xor_sync(0xffffffffu, acc[ee], o);
    if (lane == 0) {
        int i0 = 0; float v0 = acc[0];
        #pragma unroll
        for (int ee = 1; ee < 8; ee++)
            if (acc[ee] > v0) { v0 = acc[ee]; i0 = ee; }
        int i1 = -1; float v1 = -INFINITY;
        #pragma unroll
        for (int ee = 0; ee < 8; ee++)
            if (ee != i0 && acc[ee] > v1) { v1 = acc[ee]; i1 = ee; }
        float w0 = 1.f / (1.f + expf(v1 - v0));
        g_eid[warp]     = i0;
        g_eid[S + warp] = i1;
        g_wgt[warp]     = w0;
        g_wgt[S + warp] = 1.f - w0;
    }
}

// ---------------- K2: capacity-aware slot assignment (one block) -------
__global__ void k_assign() {
    __shared__ int hist[256][8];
    const int t = threadIdx.x;
    for (int i = t; i < E * CAP; i += 256) g_src[i] = -1;
    int h[8] = {0, 0, 0, 0, 0, 0, 0, 0};
    const int base = t * 64;
    for (int j = 0; j < 64; j++) h[g_eid[base + j]]++;
    #pragma unroll
    for (int ee = 0; ee < 8; ee++) hist[t][ee] = h[ee];
    __syncthreads();
    if (t < 8) {
        int run = 0;
        for (int c = 0; c < 256; c++) {
            int v = hist[c][t];
            hist[c][t] = run;
            run += v;
        }
    }
    __syncthreads();
    int cnt[8];
    #pragma unroll
    for (int ee = 0; ee < 8; ee++) cnt[ee] = hist[t][ee];
    for (int j = 0; j < 64; j++) {
        int n = base + j;
        int e = g_eid[n];
        int loc = cnt[e]++;
        if (loc < CAP) {
            g_src[e * CAP + loc] = n & (S - 1);
            g_tokslot[n] = e * CAP + loc;
        } else {
            g_tokslot[n] = -1;
        }
    }
}

// ---------------- K2b: gather tokens into bf16 hi/lo A ------------------
__global__ void k_gather(const float* __restrict__ x) {
    const int row  = blockIdx.x * 8 + (threadIdx.x >> 5);  // grid = E*CAP/8
    const int lane = threadIdx.x & 31;
    const int stok = g_src[row];
    __nv_bfloat16* oh = g_ah + (size_t)row * D;
    __nv_bfloat16* ol = g_al + (size_t)row * D;
    if (stok < 0) {
        const uint2 z = make_uint2(0u, 0u);
        for (int i = lane * 4; i < D; i += 128) {
            *(uint2*)(oh + i) = z;
            *(uint2*)(ol + i) = z;
        }
        return;
    }
    const float* xr = x + (size_t)stok * D;
    for (int i = lane * 4; i < D; i += 128) {
        float4 v = *(const float4*)(xr + i);
        __nv_bfloat16 h0 = __float2bfloat16(v.x), h1 = __float2bfloat16(v.y);
        __nv_bfloat16 h2 = __float2bfloat16(v.z), h3 = __float2bfloat16(v.w);
        __nv_bfloat16 l0 = __float2bfloat16(v.x - __bfloat162float(h0));
        __nv_bfloat16 l1 = __float2bfloat16(v.y - __bfloat162float(h1));
        __nv_bfloat16 l2 = __float2bfloat16(v.z - __bfloat162float(h2));
        __nv_bfloat16 l3 = __float2bfloat16(v.w - __bfloat162float(h3));
        union { __nv_bfloat162 b[2]; uint2 u; } ph, pl;
        ph.b[0] = __nv_bfloat162(h0, h1); ph.b[1] = __nv_bfloat162(h2, h3);
        pl.b[0] = __nv_bfloat162(l0, l1); pl.b[1] = __nv_bfloat162(l2, l3);
        *(uint2*)(oh + i) = ph.u;
        *(uint2*)(ol + i) = pl.u;
    }
}

// ---------------- K3: HMMA expert GEMM + fused epilogue -----------------
// grid = (H/128, CAP/128, E). 3-pass bf16 hi/lo mma.sync with fp32 accum.
// Smem row layout (per stage, per operand): 128 rows x 128 B, each row =
// [32 hi bf16 | 32 lo bf16], SW128-swizzled -> ldmatrix conflict-free.
__global__ void __launch_bounds__(256, 1)
k_ffn_mma(const float* __restrict__ b1) {
    extern __shared__ char smem[];
    const uint32_t sA = s2u(smem);
    const uint32_t sB = sA + STAGES * ASTAGE;
    const int e  = blockIdx.z;
    const int m0 = blockIdx.y * MT;
    const int n0 = blockIdx.x * NTT;
    const int t  = threadIdx.x;
    const int lane = t & 31;
    const int wid  = t >> 5;
    const int warpM = wid >> 2;       // 0..1  (64 rows each)
    const int warpN = wid & 3;        // 0..3  (32 cols each)

    const char* pAh = (const char*)(g_ah + (size_t)(e * CAP + m0) * D);
    const char* pAl = (const char*)(g_al + (size_t)(e * CAP + m0) * D);
    const char* pBh = (const char*)(g_w1h + ((size_t)e * H + n0) * D);
    const char* pBl = (const char*)(g_w1l + ((size_t)e * H + n0) * D);
    const size_t RS = (size_t)D * 2;  // 4096 B global row stride

    // per-thread load coords (8 chunks of 16B per operand per stage)
    const int lrow  = t >> 3;          // base row (32 rows per 256-thr pass)
    const int lpart = t & 7;           // chunk within 128-B row
    const int lhi   = (lpart < 4);
    const int lgofs = lhi ? lpart * 16 : (lpart - 4) * 16;

    auto load_stage = [&](int st, int buf) {
        const size_t kb = (size_t)st * (KTILE * 2);
        #pragma unroll
        for (int j = 0; j < 4; j++) {
            int row = lrow + 32 * j;
            uint32_t so = swz((uint32_t)(row * 128 + lpart * 16));
            size_t go = (size_t)row * RS + kb + lgofs;
            cpa16(sA + buf * ASTAGE + so, (lhi ? pAh : pAl) + go);
            cpa16(sB + buf * BSTAGE + so, (lhi ? pBh : pBl) + go);
        }
    };

    float acc[4][4][4];
    #pragma unroll
    for (int i = 0; i < 4; i++)
        #pragma unroll
        for (int j = 0; j < 4; j++)
            #pragma unroll
            for (int q = 0; q < 4; q++) acc[i][j][q] = 0.f;

    // ldmatrix per-lane base offsets (unswizzled)
    const uint32_t aBase = (uint32_t)((warpM * 64 + (lane & 15)) * 128 +
                                      ((lane >> 4) << 4));
    const int brow = warpN * 32 + (lane & 7) + ((lane & 16) >> 1);
    const uint32_t bBase = (uint32_t)(brow * 128 + ((lane & 8) << 1));

    // prologue: stages 0..2
    #pragma unroll
    for (int st = 0; st < STAGES - 1; st++) {
        load_stage(st, st);
        cp_commit();
    }

    #pragma unroll 1
    for (int it = 0; it < NK; it++) {
        cp_wait<STAGES - 2>();
        __syncthreads();
        if (it + STAGES - 1 < NK) load_stage(it + STAGES - 1, (it + STAGES - 1) & (STAGES - 1));
        cp_commit();

        const int buf = it & (STAGES - 1);
        const uint32_t abuf = sA + buf * ASTAGE;
        const uint32_t bbuf = sB + buf * BSTAGE;
        #pragma unroll
        for (int s = 0; s < 2; s++) {
            uint32_t ah[4][4], al[4][4], bh[2][4], bl[2][4];
            #pragma unroll
            for (int mt = 0; mt < 4; mt++) {
                uint32_t off = aBase + mt * 2048 + s * 32;
                ldsm4(ah[mt], abuf + swz(off));
                ldsm4(al[mt], abuf + swz(off + 64));
            }
            #pragma unroll
            for (int np = 0; np < 2; np++) {
                uint32_t off = bBase + np * 2048 + s * 32;
                ldsm4(bh[np], bbuf + swz(off));
                ldsm4(bl[np], bbuf + swz(off + 64));
            }
            #pragma unroll
            for (int mt = 0; mt < 4; mt++)
                #pragma unroll
                for (int nt = 0; nt < 4; nt++) {
                    const int np = nt >> 1, o = (nt & 1) * 2;
                    mma16816(acc[mt][nt], ah[mt], bh[np][o], bh[np][o + 1]);
                    mma16816(acc[mt][nt], ah[mt], bl[np][o], bl[np][o + 1]);
                    mma16816(acc[mt][nt], al[mt], bh[np][o], bh[np][o + 1]);
                }
        }
    }

    // ---- epilogue: relu(acc + b1) . w2sum, reduce over 128 N ----
    __syncthreads();                       // all compute done; reuse smem
    float* red = (float*)smem;             // [128][4]
    const int g  = lane >> 2;
    const int t4 = lane & 3;
    const float* b1p = b1 + (size_t)e * H + n0;
    const float* wp  = g_w2sum + (size_t)e * H + n0;
    #pragma unroll
    for (int mt = 0; mt < 4; mt++) {
        float sAcc = 0.f, sBcc = 0.f;
        #pragma unroll
        for (int nt = 0; nt < 4; nt++) {
            int ni = warpN * 32 + nt * 8 + t4 * 2;
            float bb0 = __ldg(b1p + ni),     ww0 = __ldg(wp + ni);
            float bb1 = __ldg(b1p + ni + 1), ww1 = __ldg(wp + ni + 1);
            sAcc += fmaxf(acc[mt][nt][0] + bb0, 0.f) * ww0 +
                    fmaxf(acc[mt][nt][1] + bb1, 0.f) * ww1;
            sBcc += fmaxf(acc[mt][nt][2] + bb0, 0.f) * ww0 +
                    fmaxf(acc[mt][nt][3] + bb1, 0.f) * ww1;
        }
        sAcc += __shfl_xor_sync(0xffffffffu, sAcc, 1);
        sAcc += __shfl_xor_sync(0xffffffffu, sAcc, 2);
        sBcc += __shfl_xor_sync(0xffffffffu, sBcc, 1);
        sBcc += __shfl_xor_sync(0xffffffffu, sBcc, 2);
        if (t4 == 0) {
            int r = warpM * 64 + mt * 16 + g;
            red[r * 4 + warpN]       = sAcc;
            red[(r + 8) * 4 + warpN] = sBcc;
        }
    }
    __syncthreads();
    if (t < 128) {
        float v = red[t * 4] + red[t * 4 + 1] + red[t * 4 + 2] + red[t * 4 + 3];
        g_part[(size_t)(e * CAP + m0 + t) * NTILES + blockIdx.x] = v;
    }
}

// ---------------- K4a: per-token logit = sum over D of y ----------------
__global__ void k_logit() {
    int s = blockIdx.x * blockDim.x + threadIdx.x;
    if (s >= S) return;
    float l = 0.f;
    #pragma unroll
    for (int k = 0; k < KK; k++) {
        int slot = g_tokslot[k * S + s];
        if (slot >= 0) {
            float c = 0.f;
            const float* p = g_part + (size_t)slot * NTILES;
            #pragma unroll
            for (int j = 0; j < NTILES; j++) c += p[j];
            l += g_wgt[k * S + s] * (c + g_b2sum[g_eid[k * S + s]]);
        }
    }
    g_logit[s] = l;
}

// ---------------- K4b: log_softmax over T per batch row -----------------
__global__ void k_lsm(float* __restrict__ out) {
    const int b = blockIdx.x;
    const int t = threadIdx.x;  // 256 threads
    __shared__ float sh[256];
    const float* lr = g_logit + (size_t)b * T;
    float v[8];
    float mx = -INFINITY;
    #pragma unroll
    for (int i = 0; i < 8; i++) {
        v[i] = lr[t + i * 256];
        mx = fmaxf(mx, v[i]);
    }
    sh[t] = mx;
    __syncthreads();
    for (int o = 128; o; o >>= 1) {
        if (t < o) sh[t] = fmaxf(sh[t], sh[t + o]);
        __syncthreads();
    }
    mx = sh[0];
    __syncthreads();
    float se = 0.f;
    #pragma unroll
    for (int i = 0; i < 8; i++) se += expf(v[i] - mx);
    sh[t] = se;
    __syncthreads();
    for (int o = 128; o; o >>= 1) {
        if (t < o) sh[t] += sh[t + o];
        __syncthreads();
    }
    float lse = logf(sh[0]) + mx;
    #pragma unroll
    for (int i = 0; i < 8; i++)
        out[(size_t)b * T + t + i * 256] = v[i] - lse;
}

// ---------------- launch ------------------------------------------------
extern "C" void kernel_launch(void* const* d_in, const int* in_sizes, int n_in,
                              void* d_out, int out_size) {
    const float* x  = (const float*)d_in[0];   // [B,T,D]
    const float* wg = (const float*)d_in[1];   // [D,E]
    const float* w1 = (const float*)d_in[2];   // [E,D,H]
    const float* b1 = (const float*)d_in[3];   // [E,H]
    const float* w2 = (const float*)d_in[4];   // [E,H,D]
    const float* b2 = (const float*)d_in[5];   // [E,D]
    float* out = (float*)d_out;                // [B,T]
    (void)in_sizes; (void)n_in; (void)out_size;

    float* w2sum_p; cudaGetSymbolAddress((void**)&w2sum_p, g_w2sum);
    float* b2sum_p; cudaGetSymbolAddress((void**)&b2sum_p, g_b2sum);

    cudaFuncSetAttribute(k_ffn_mma,
                         cudaFuncAttributeMaxDynamicSharedMemorySize, SMEM_FFN);

    // weight prep (independent of tokens)
    k_rowsum<<<(E * H) / 8, 256>>>(w2, w2sum_p, E * H);
    k_rowsum<<<1, 256>>>(b2, b2sum_p, E);
    k_convw1<<<dim3(H / 32, D / 32, E), 256>>>(w1);

    // gating + assignment + gather
    k_gate<<<S / 8, 256>>>(x, wg);
    k_assign<<<1, 256>>>();
    k_gather<<<(E * CAP) / 8, 256>>>(x);

    // tensor-core grouped GEMM + fused epilogue
    k_ffn_mma<<<dim3(H / NTT, CAP / MT, E), 256, SMEM_FFN>>>(b1);

    // combine + log_softmax
    k_logit<<<S / 256, 256>>>();
    k_lsm<<<B, 256>>>(out);
}

// round 7
// speedup vs baseline: 6.4571x; 2.4378x over previous
#include <cuda_runtime.h>
#include <cuda_fp16.h>
#include <cstdint>
#include <math.h>

// Problem dims (fixed by the dataset)
constexpr int S  = 8192;   // B*T tokens
constexpr int D  = 2048;   // model dim
constexpr int H  = 2048;   // expert hidden
constexpr int E  = 8;      // experts
constexpr int KK = 2;      // top-k
constexpr int CAP = 2048;  // per-expert capacity
constexpr int B  = 4;
constexpr int T  = 2048;

// GEMM tiling (HMMA fp16 1-pass: CTA 128x128, 8 warps = 2M x 4N)
constexpr int MT = 128;
constexpr int NTT = 128;
constexpr int KTILE = 32;            // k elements per stage
constexpr int STAGES = 5;
constexpr int NK = D / KTILE;        // 64 iterations
constexpr int NTILES = H / NTT;      // 16 N-tiles per expert row
constexpr int ASTAGE = MT * 64;      // 8192 B (row = 32 fp16 = 64 B)
constexpr int BSTAGE = NTT * 64;     // 8192 B
constexpr int SMEM_FFN = STAGES * (ASTAGE + BSTAGE);  // 81920 B

// ---------------- device scratch (no allocations allowed) ----------------
__device__ int   g_eid[KK * S];
__device__ float g_wgt[KK * S];
__device__ int   g_src[E * CAP];       // slot -> source token (-1 = empty)
__device__ int   g_tokslot[KK * S];    // (k,s) -> slot index or -1
__device__ float g_w2sum[E * H];
__device__ float g_b2sum[E];
__device__ float g_part[(size_t)E * CAP * NTILES];
__device__ float g_logit[S];
__device__ __half g_ah[(size_t)E * CAP * D];    // gathered tokens (fp16)
__device__ __half g_w1h[(size_t)E * H * D];     // w1^T [E][H][D] (fp16)

// ---------------- PTX helpers (baseline ISA: sm_80-class) ---------------
__device__ __forceinline__ uint32_t s2u(const void* p) {
    return (uint32_t)__cvta_generic_to_shared(p);
}
__device__ __forceinline__ void cpa16(uint32_t s, const void* g) {
    asm volatile("cp.async.cg.shared.global [%0], [%1], 16;" :: "r"(s), "l"(g));
}
__device__ __forceinline__ void cp_commit() {
    asm volatile("cp.async.commit_group;" ::: "memory");
}
template <int N>
__device__ __forceinline__ void cp_wait() {
    asm volatile("cp.async.wait_group %0;" :: "n"(N) : "memory");
}
__device__ __forceinline__ void ldsm4(uint32_t* r, uint32_t addr) {
    asm volatile("ldmatrix.sync.aligned.m8n8.x4.shared.b16 {%0,%1,%2,%3}, [%4];"
                 : "=r"(r[0]), "=r"(r[1]), "=r"(r[2]), "=r"(r[3]) : "r"(addr));
}
__device__ __forceinline__ void mma16816(float* c, const uint32_t* a,
                                         uint32_t b0, uint32_t b1) {
    asm volatile(
        "mma.sync.aligned.m16n8k16.row.col.f32.f16.f16.f32 "
        "{%0,%1,%2,%3}, {%4,%5,%6,%7}, {%8,%9}, {%0,%1,%2,%3};"
        : "+f"(c[0]), "+f"(c[1]), "+f"(c[2]), "+f"(c[3])
        : "r"(a[0]), "r"(a[1]), "r"(a[2]), "r"(a[3]), "r"(b0), "r"(b1));
}
__device__ __forceinline__ uint32_t swz64(uint32_t off) {
    return off ^ ((off >> 3) & 0x30);
}

// ---------------- K0: row sums of w2 (and b2) --------------------------
__global__ void k_rowsum(const float* __restrict__ src, float* __restrict__ dst,
                         int nrows) {
    int gw   = (blockIdx.x * blockDim.x + threadIdx.x) >> 5;
    int lane = threadIdx.x & 31;
    if (gw >= nrows) return;
    const float* row = src + (size_t)gw * D;
    float s = 0.f;
    #pragma unroll
    for (int d = lane * 4; d < D; d += 32 * 4) {
        float4 v = *(const float4*)(row + d);
        s += v.x + v.y + v.z + v.w;
    }
    #pragma unroll
    for (int o = 16; o; o >>= 1) s += __shfl_xor_sync(0xffffffffu, s, o);
    if (lane == 0) dst[gw] = s;
}

// ---------------- K0b: w1 transpose + fp16 convert ----------------------
__global__ void k_convw1(const float* __restrict__ w1) {
    __shared__ float ts[32][33];
    const int e  = blockIdx.z;
    const int h0 = blockIdx.x * 32;
    const int d0 = blockIdx.y * 32;
    const int tx = threadIdx.x & 31, ty = threadIdx.x >> 5;  // 256 thr
    #pragma unroll
    for (int j = 0; j < 4; j++)
        ts[ty + 8 * j][tx] = w1[((size_t)e * D + d0 + ty + 8 * j) * H + h0 + tx];
    __syncthreads();
    #pragma unroll
    for (int j = 0; j < 4; j++) {
        float v = ts[tx][ty + 8 * j];
        size_t o = ((size_t)e * H + h0 + ty + 8 * j) * D + d0 + tx;
        g_w1h[o] = __float2half(v);
    }
}

// ---------------- K1: gating (top-2 of softmax(x@wg), normalized) ------
// wg staged into smem transposed: swg[e][d] (conflict-free float4 reads).
__global__ void k_gate(const float* __restrict__ x, const float* __restrict__ wg) {
    extern __shared__ float swg[];   // [8][2048] = 64 KB
    const int t = threadIdx.x;       // 256
    for (int i = t; i < D * E; i += 256) {
        int d = i >> 3, e = i & 7;
        swg[e * D + d] = wg[i];
    }
    __syncthreads();

    const int warp = blockIdx.x * 8 + (t >> 5);
    const int lane = t & 31;
    const float* xr = x + (size_t)warp * D;
    float acc[8] = {0, 0, 0, 0, 0, 0, 0, 0};
    for (int d = lane * 4; d < D; d += 128) {
        float4 xv = *(const float4*)(xr + d);
        #pragma unroll
        for (int e = 0; e < 8; e++) {
            float4 w = *(const float4*)&swg[e * D + d];
            acc[e] = fmaf(xv.x, w.x, acc[e]);
            acc[e] = fmaf(xv.y, w.y, acc[e]);
            acc[e] = fmaf(xv.z, w.z, acc[e]);
            acc[e] = fmaf(xv.w, w.w, acc[e]);
        }
    }
    #pragma unroll
    for (int ee = 0; ee < 8; ee++)
        #pragma unroll
        for (int o = 16; o; o >>= 1)
            acc[ee] += __shfl_xor_sync(0xffffffffu, acc[ee], o);
    if (lane == 0) {
        int i0 = 0; float v0 = acc[0];
        #pragma unroll
        for (int ee = 1; ee < 8; ee++)
            if (acc[ee] > v0) { v0 = acc[ee]; i0 = ee; }
        int i1 = -1; float v1 = -INFINITY;
        #pragma unroll
        for (int ee = 0; ee < 8; ee++)
            if (ee != i0 && acc[ee] > v1) { v1 = acc[ee]; i1 = ee; }
        float w0 = 1.f / (1.f + expf(v1 - v0));
        g_eid[warp]     = i0;
        g_eid[S + warp] = i1;
        g_wgt[warp]     = w0;
        g_wgt[S + warp] = 1.f - w0;
    }
}

// ---------------- K2: capacity-aware slot assignment (one block) -------
// 1024 threads; exact k-major, s-minor rank per expert (cumsum semantics).
__global__ void k_assign() {
    __shared__ int hist[1024][8];
    const int t = threadIdx.x;
    for (int i = t; i < E * CAP; i += 1024) g_src[i] = -1;
    int h[8] = {0, 0, 0, 0, 0, 0, 0, 0};
    const int base = t * 16;
    #pragma unroll
    for (int j = 0; j < 16; j++) h[g_eid[base + j]]++;
    #pragma unroll
    for (int ee = 0; ee < 8; ee++) hist[t][ee] = h[ee];
    __syncthreads();
    // warp w computes the exclusive prefix over 1024 chunks for expert w
    const int wid = t >> 5, lane = t & 31;
    if (wid < 8) {
        int p = 0;
        #pragma unroll
        for (int j = 0; j < 32; j++) p += hist[lane * 32 + j][wid];
        int ex = p;
        #pragma unroll
        for (int o = 1; o < 32; o <<= 1) {
            int v = __shfl_up_sync(0xffffffffu, ex, o);
            if (lane >= o) ex += v;
        }
        ex -= p;  // exclusive
        int run = ex;
        #pragma unroll
        for (int j = 0; j < 32; j++) {
            int v = hist[lane * 32 + j][wid];
            hist[lane * 32 + j][wid] = run;
            run += v;
        }
    }
    __syncthreads();
    int cnt[8];
    #pragma unroll
    for (int ee = 0; ee < 8; ee++) cnt[ee] = hist[t][ee];
    #pragma unroll
    for (int j = 0; j < 16; j++) {
        int n = base + j;
        int e = g_eid[n];
        int loc = cnt[e]++;
        if (loc < CAP) {
            g_src[e * CAP + loc] = n & (S - 1);
            g_tokslot[n] = e * CAP + loc;
        } else {
            g_tokslot[n] = -1;
        }
    }
}

// ---------------- K2b: gather tokens into fp16 A ------------------------
__global__ void k_gather(const float* __restrict__ x) {
    const int row  = blockIdx.x * 8 + (threadIdx.x >> 5);  // grid = E*CAP/8
    const int lane = threadIdx.x & 31;
    const int stok = g_src[row];
    __half* oh = g_ah + (size_t)row * D;
    if (stok < 0) {
        const uint2 z = make_uint2(0u, 0u);
        for (int i = lane * 8; i < D; i += 256)
            *(uint2*)(oh + i) = z;
        return;
    }
    const float* xr = x + (size_t)stok * D;
    for (int i = lane * 8; i < D; i += 256) {
        float4 v0 = *(const float4*)(xr + i);
        float4 v1 = *(const float4*)(xr + i + 4);
        union { __half2 h[4]; uint2 u[2]; } p;
        p.h[0] = __floats2half2_rn(v0.x, v0.y);
        p.h[1] = __floats2half2_rn(v0.z, v0.w);
        p.h[2] = __floats2half2_rn(v1.x, v1.y);
        p.h[3] = __floats2half2_rn(v1.z, v1.w);
        *(uint2*)(oh + i)     = p.u[0];
        *(uint2*)(oh + i + 4) = p.u[1];
    }
}

// ---------------- K3: fp16 HMMA expert GEMM + fused epilogue ------------
// grid = (H/128, CAP/128, E). Single-pass fp16 mma.sync, fp32 accum.
// Smem rows: 64 B (32 fp16, k-tile 32), SW64 swizzle, conflict-free ldmatrix.
__global__ void __launch_bounds__(256, 2)
k_ffn_mma(const float* __restrict__ b1) {
    extern __shared__ char smem[];
    const uint32_t sA = s2u(smem);
    const uint32_t sB = sA + STAGES * ASTAGE;
    const int e  = blockIdx.z;
    const int m0 = blockIdx.y * MT;
    const int n0 = blockIdx.x * NTT;
    const int t  = threadIdx.x;
    const int lane = t & 31;
    const int wid  = t >> 5;
    const int warpM = wid >> 2;       // 0..1  (64 rows each)
    const int warpN = wid & 3;        // 0..3  (32 cols each)

    const char* pA = (const char*)(g_ah + (size_t)(e * CAP + m0) * D);
    const char* pB = (const char*)(g_w1h + ((size_t)e * H + n0) * D);
    const size_t RS = (size_t)D * 2;  // 4096 B global row stride

    // per-thread load coords: 512 chunks of 16B per operand per stage
    auto load_stage = [&](int st, int buf) {
        const size_t kb = (size_t)st * (KTILE * 2);
        #pragma unroll
        for (int j = 0; j < 2; j++) {
            int idx = t + 256 * j;
            int row = idx >> 2, c = idx & 3;
            uint32_t so = swz64((uint32_t)(row * 64 + c * 16));
            size_t go = (size_t)row * RS + kb + c * 16;
            cpa16(sA + buf * ASTAGE + so, pA + go);
            cpa16(sB + buf * BSTAGE + so, pB + go);
        }
    };

    float acc[4][4][4];
    #pragma unroll
    for (int i = 0; i < 4; i++)
        #pragma unroll
        for (int j = 0; j < 4; j++)
            #pragma unroll
            for (int q = 0; q < 4; q++) acc[i][j][q] = 0.f;

    // ldmatrix per-lane base offsets (unswizzled)
    const uint32_t aBase = (uint32_t)((warpM * 64 + (lane & 15)) * 64 +
                                      ((lane >> 4) << 4));
    const int brow = warpN * 32 + (lane & 7) + ((lane & 16) >> 1);
    const uint32_t bBase = (uint32_t)(brow * 64 + ((lane & 8) << 1));

    // prologue: stages 0..STAGES-2
    #pragma unroll
    for (int st = 0; st < STAGES - 1; st++) {
        load_stage(st, st);
        cp_commit();
    }

    #pragma unroll 1
    for (int it = 0; it < NK; it++) {
        cp_wait<STAGES - 2>();
        __syncthreads();
        if (it + STAGES - 1 < NK) {
            int st = it + STAGES - 1;
            load_stage(st, st % STAGES);
        }
        cp_commit();

        const int buf = it % STAGES;
        const uint32_t abuf = sA + buf * ASTAGE;
        const uint32_t bbuf = sB + buf * BSTAGE;
        #pragma unroll
        for (int s = 0; s < 2; s++) {
            uint32_t a[4][4], b[2][4];
            #pragma unroll
            for (int mt = 0; mt < 4; mt++)
                ldsm4(a[mt], abuf + swz64(aBase + mt * 1024 + s * 32));
            #pragma unroll
            for (int np = 0; np < 2; np++)
                ldsm4(b[np], bbuf + swz64(bBase + np * 1024 + s * 32));
            #pragma unroll
            for (int mt = 0; mt < 4; mt++)
                #pragma unroll
                for (int nt = 0; nt < 4; nt++) {
                    const int np = nt >> 1, o = (nt & 1) * 2;
                    mma16816(acc[mt][nt], a[mt], b[np][o], b[np][o + 1]);
                }
        }
    }

    // ---- epilogue: relu(acc + b1) . w2sum, reduce over 128 N ----
    __syncthreads();                       // all loads retired; reuse smem
    float* red = (float*)smem;             // [128][4]
    const int g  = lane >> 2;
    const int t4 = lane & 3;
    const float* b1p = b1 + (size_t)e * H + n0;
    const float* wp  = g_w2sum + (size_t)e * H + n0;
    #pragma unroll
    for (int mt = 0; mt < 4; mt++) {
        float sAcc = 0.f, sBcc = 0.f;
        #pragma unroll
        for (int nt = 0; nt < 4; nt++) {
            int ni = warpN * 32 + nt * 8 + t4 * 2;
            float bb0 = __ldg(b1p + ni),     ww0 = __ldg(wp + ni);
            float bb1 = __ldg(b1p + ni + 1), ww1 = __ldg(wp + ni + 1);
            sAcc += fmaxf(acc[mt][nt][0] + bb0, 0.f) * ww0 +
                    fmaxf(acc[mt][nt][1] + bb1, 0.f) * ww1;
            sBcc += fmaxf(acc[mt][nt][2] + bb0, 0.f) * ww0 +
                    fmaxf(acc[mt][nt][3] + bb1, 0.f) * ww1;
        }
        sAcc += __shfl_xor_sync(0xffffffffu, sAcc, 1);
        sAcc += __shfl_xor_sync(0xffffffffu, sAcc, 2);
        sBcc += __shfl_xor_sync(0xffffffffu, sBcc, 1);
        sBcc += __shfl_xor_sync(0xffffffffu, sBcc, 2);
        if (t4 == 0) {
            int r = warpM * 64 + mt * 16 + g;
            red[r * 4 + warpN]       = sAcc;
            red[(r + 8) * 4 + warpN] = sBcc;
        }
    }
    __syncthreads();
    if (t < 128) {
        float v = red[t * 4] + red[t * 4 + 1] + red[t * 4 + 2] + red[t * 4 + 3];
        g_part[(size_t)(e * CAP + m0 + t) * NTILES + blockIdx.x] = v;
    }
}

// ---------------- K4a: per-token logit = sum over D of y ----------------
__global__ void k_logit() {
    int s = blockIdx.x * blockDim.x + threadIdx.x;
    if (s >= S) return;
    float l = 0.f;
    #pragma unroll
    for (int k = 0; k < KK; k++) {
        int slot = g_tokslot[k * S + s];
        if (slot >= 0) {
            float c = 0.f;
            const float* p = g_part + (size_t)slot * NTILES;
            #pragma unroll
            for (int j = 0; j < NTILES; j++) c += p[j];
            l += g_wgt[k * S + s] * (c + g_b2sum[g_eid[k * S + s]]);
        }
    }
    g_logit[s] = l;
}

// ---------------- K4b: log_softmax over T per batch row -----------------
__global__ void k_lsm(float* __restrict__ out) {
    const int b = blockIdx.x;
    const int t = threadIdx.x;  // 256 threads
    __shared__ float sh[256];
    const float* lr = g_logit + (size_t)b * T;
    float v[8];
    float mx = -INFINITY;
    #pragma unroll
    for (int i = 0; i < 8; i++) {
        v[i] = lr[t + i * 256];
        mx = fmaxf(mx, v[i]);
    }
    sh[t] = mx;
    __syncthreads();
    for (int o = 128; o; o >>= 1) {
        if (t < o) sh[t] = fmaxf(sh[t], sh[t + o]);
        __syncthreads();
    }
    mx = sh[0];
    __syncthreads();
    float se = 0.f;
    #pragma unroll
    for (int i = 0; i < 8; i++) se += expf(v[i] - mx);
    sh[t] = se;
    __syncthreads();
    for (int o = 128; o; o >>= 1) {
        if (t < o) sh[t] += sh[t + o];
        __syncthreads();
    }
    float lse = logf(sh[0]) + mx;
    #pragma unroll
    for (int i = 0; i < 8; i++)
        out[(size_t)b * T + t + i * 256] = v[i] - lse;
}

// ---------------- launch ------------------------------------------------
extern "C" void kernel_launch(void* const* d_in, const int* in_sizes, int n_in,
                              void* d_out, int out_size) {
    const float* x  = (const float*)d_in[0];   // [B,T,D]
    const float* wg = (const float*)d_in[1];   // [D,E]
    const float* w1 = (const float*)d_in[2];   // [E,D,H]
    const float* b1 = (const float*)d_in[3];   // [E,H]
    const float* w2 = (const float*)d_in[4];   // [E,H,D]
    const float* b2 = (const float*)d_in[5];   // [E,D]
    float* out = (float*)d_out;                // [B,T]
    (void)in_sizes; (void)n_in; (void)out_size;

    float* w2sum_p; cudaGetSymbolAddress((void**)&w2sum_p, g_w2sum);
    float* b2sum_p; cudaGetSymbolAddress((void**)&b2sum_p, g_b2sum);

    cudaFuncSetAttribute(k_ffn_mma,
                         cudaFuncAttributeMaxDynamicSharedMemorySize, SMEM_FFN);
    cudaFuncSetAttribute(k_gate,
                         cudaFuncAttributeMaxDynamicSharedMemorySize, D * E * 4);

    // weight prep (independent of tokens)
    k_rowsum<<<(E * H) / 8, 256>>>(w2, w2sum_p, E * H);
    k_rowsum<<<1, 256>>>(b2, b2sum_p, E);
    k_convw1<<<dim3(H / 32, D / 32, E), 256>>>(w1);

    // gating + assignment + gather
    k_gate<<<S / 8, 256, D * E * 4>>>(x, wg);
    k_assign<<<1, 1024>>>();
    k_gather<<<(E * CAP) / 8, 256>>>(x);

    // tensor-core grouped GEMM + fused epilogue
    k_ffn_mma<<<dim3(H / NTT, CAP / MT, E), 256, SMEM_FFN>>>(b1);

    // combine + log_softmax
    k_logit<<<S / 256, 256>>>();
    k_lsm<<<B, 256>>>(out);
}